// round 9
// baseline (speedup 1.0000x reference)
#include <cuda_runtime.h>
#include <cuda_bf16.h>
#include <math.h>
#include <stdint.h>

#define B_SZ   2048
#define C_SZ   512
#define N_SZ   256
#define F_SZ   256
#define K_TOP  4
#define LOG_F  5.545177444479562f

// ---------------- scratch (static device memory; no allocation) ----------------
__device__ __align__(16) __nv_bfloat16 g_xn  [B_SZ * C_SZ];
__device__ __align__(16) __nv_bfloat16 g_h1  [B_SZ * C_SZ];
__device__ __align__(16) __nv_bfloat16 g_h2  [B_SZ * C_SZ];
__device__ __align__(16) float         g_coarse[B_SZ * N_SZ];
__device__ __align__(16) int           g_topidx[B_SZ * K_TOP];
__device__ __align__(16) float         g_t1  [B_SZ * C_SZ];
__device__ __align__(16) __nv_bfloat16 g_e   [B_SZ * K_TOP * C_SZ];
__device__ __align__(16) __nv_bfloat16 g_g1  [B_SZ * K_TOP * C_SZ];
__device__ __align__(16) __nv_bfloat16 g_g2  [B_SZ * K_TOP * C_SZ];
__device__ __align__(16) float         g_fine[B_SZ * K_TOP * F_SZ];
__device__ __align__(16) __nv_bfloat16 g_wbf [1572864];

// work-queue state (zeroed by zero_ctrs each replay)
__device__ int g_tick[8];
__device__ int g_done[8];

#define W_CW1  0
#define W_CW2  262144
#define W_CW3  524288
#define W_FW1A 655360
#define W_FW1B 917504
#define W_FW2  1179648
#define W_FW3  1441792

// phases
#define PH_TOPK 0
#define PH_EMB  1
#define PH_G1   2
#define PH_G2   3
#define PH_G3   4
#define PH_FILL 5
#define PH_SCAT 6
#define CNT_TOPK 256
#define CNT_EMB  1024
#define CNT_G1   512
#define CNT_G2   512
#define CNT_G3   256
#define CNT_FILL 8192
#define CNT_SCAT 1024

// ---------------- PTX helpers ----------------
__device__ __forceinline__ uint32_t smem_to_u32(const void* p) {
    uint32_t a;
    asm("{ .reg .u64 t; cvta.to.shared.u64 t, %1; cvt.u32.u64 %0, t; }" : "=r"(a) : "l"(p));
    return a;
}
#define CP16(dst, src)    asm volatile("cp.async.cg.shared.global [%0], [%1], 16;" :: "r"(dst), "l"(src))
#define CP_COMMIT()       asm volatile("cp.async.commit_group;" ::: "memory")
#define CP_WAIT(n)        asm volatile("cp.async.wait_group %0;" :: "n"(n) : "memory")

#define LDSM4(r, addr)                                                           \
    asm volatile("ldmatrix.sync.aligned.m8n8.x4.shared.b16 {%0,%1,%2,%3}, [%4];" \
        : "=r"((r)[0]), "=r"((r)[1]), "=r"((r)[2]), "=r"((r)[3]) : "r"(addr))

__device__ __forceinline__ void mma16816(float* d, const uint32_t* a,
                                         uint32_t b0, uint32_t b1) {
    asm volatile("mma.sync.aligned.m16n8k16.row.col.f32.bf16.bf16.f32 "
        "{%0,%1,%2,%3}, {%4,%5,%6,%7}, {%8,%9}, {%0,%1,%2,%3};"
        : "+f"(d[0]), "+f"(d[1]), "+f"(d[2]), "+f"(d[3])
        : "r"(a[0]), "r"(a[1]), "r"(a[2]), "r"(a[3]), "r"(b0), "r"(b1));
}

// ---------------- misc helpers ----------------
__device__ __forceinline__ float warp_sum(float v) {
    #pragma unroll
    for (int o = 16; o; o >>= 1) v += __shfl_xor_sync(0xffffffffu, v, o);
    return v;
}
__device__ __forceinline__ float warp_max(float v) {
    #pragma unroll
    for (int o = 16; o; o >>= 1) v = fmaxf(v, __shfl_xor_sync(0xffffffffu, v, o));
    return v;
}
__device__ __forceinline__ float gelu_tanh(float x) {
    float x3 = x * x * x;
    return 0.5f * x * (1.0f + tanhf(0.7978845608028654f * (x + 0.044715f * x3)));
}

// ---------------- merged transpose + fp32 -> bf16 over all weights ----------------
struct CvtArgs {
    const float*   W[7];
    __nv_bfloat16* Wt[7];
    int K[7], N[7], start[7];
};
__global__ void cvtT_multi(CvtArgs a) {
    __shared__ float t[32][33];
    int seg = 0;
    #pragma unroll
    for (int s = 1; s < 7; s++) if ((int)blockIdx.x >= a.start[s]) seg = s;
    int tile = blockIdx.x - a.start[seg];
    int K = a.K[seg], N = a.N[seg];
    int ntx = N >> 5;
    int n0 = (tile % ntx) * 32, k0 = (tile / ntx) * 32;
    const float* W = a.W[seg];
    __nv_bfloat16* Wt = a.Wt[seg];
    int tx = threadIdx.x, ty = threadIdx.y;
    #pragma unroll
    for (int i = 0; i < 4; i++)
        t[ty + i * 8][tx] = W[(size_t)(k0 + ty + i * 8) * N + n0 + tx];
    __syncthreads();
    #pragma unroll
    for (int i = 0; i < 4; i++)
        Wt[(size_t)(n0 + ty + i * 8) * K + k0 + tx] = __float2bfloat16(t[tx][ty + i * 8]);
}

__global__ void zero_ctrs() {
    if (threadIdx.x < 8) { g_tick[threadIdx.x] = 0; g_done[threadIdx.x] = 0; }
}

// ---------------- LayerNorm(x) + no_op head ----------------
__global__ void ln_noop_kernel(const float* __restrict__ x,
                               const float* __restrict__ g, const float* __restrict__ b,
                               const float* __restrict__ nw, const float* __restrict__ nb,
                               __nv_bfloat16* __restrict__ xn, float* __restrict__ out) {
    int row = blockIdx.x, t = threadIdx.x;
    int w = t >> 5, lane = t & 31;
    float4 v = ((const float4*)(x + (size_t)row * C_SZ))[t];

    float s  = v.x + v.y + v.z + v.w;
    float sq = v.x * v.x + v.y * v.y + v.z * v.z + v.w * v.w;

    __shared__ float rs[4], rq[4], rn[4];
    float ws = warp_sum(s), wq = warp_sum(sq);
    if (lane == 0) { rs[w] = ws; rq[w] = wq; }
    __syncthreads();
    float tot_s = rs[0] + rs[1] + rs[2] + rs[3];
    float tot_q = rq[0] + rq[1] + rq[2] + rq[3];
    float mean = tot_s * (1.0f / C_SZ);
    float var  = tot_q * (1.0f / C_SZ) - mean * mean;
    float rstd = rsqrtf(var + 1e-5f);

    float4 gg = ((const float4*)g)[t];
    float4 bb = ((const float4*)b)[t];
    float y0 = (v.x - mean) * rstd * gg.x + bb.x;
    float y1 = (v.y - mean) * rstd * gg.y + bb.y;
    float y2 = (v.z - mean) * rstd * gg.z + bb.z;
    float y3 = (v.w - mean) * rstd * gg.w + bb.w;

    __nv_bfloat16* xr = xn + (size_t)row * C_SZ + t * 4;
    ((__nv_bfloat162*)xr)[0] = __floats2bfloat162_rn(y0, y1);
    ((__nv_bfloat162*)xr)[1] = __floats2bfloat162_rn(y2, y3);

    float4 ww = ((const float4*)nw)[t];
    float acc = y0 * ww.x + y1 * ww.y + y2 * ww.z + y3 * ww.w;
    float wacc = warp_sum(acc);
    if (lane == 0) rn[w] = wacc;
    __syncthreads();
    if (t == 0) out[(size_t)row * 65537] = rn[0] + rn[1] + rn[2] + rn[3] + nb[0];
}

// ---------------- shared GEMM tile worker (64x128 CTA tile) ----------------
#define GT_THREADS 256
#define GT_STAGE   24576
#define GT_SMEM    (3 * GT_STAGE + 1024)

struct GArgs {
    const __nv_bfloat16* A;
    const __nv_bfloat16* Bw;
    const float* bias;
    const float* addrow;
    __nv_bfloat16* outb;
    float* outf;
    int K, N, gridn, gelu;
};

__device__ __forceinline__ void gemm_item(const GArgs& a, int cta, uint32_t base, int tid) {
    int bm = cta / a.gridn, bn = cta % a.gridn;
    const int K = a.K, N = a.N;
    const int NC = K >> 6;

    int warp = tid >> 5, lane = tid & 31;
    int wm = warp >> 2, wn = warp & 3;

    auto load_chunk = [&](int c) {
        uint32_t sb = base + (c % 3) * GT_STAGE;
        const __nv_bfloat16* Ap = a.A  + (size_t)bm * 64 * K + (size_t)c * 64;
        const __nv_bfloat16* Bp = a.Bw + (size_t)bn * 128 * K + (size_t)c * 64;
        #pragma unroll
        for (int i = 0; i < 2; i++) {
            int id = tid + i * 256;
            int r = id >> 3, j = id & 7;
            uint32_t off = (uint32_t)(r * 128 + j * 16);
            uint32_t sw = off ^ ((off >> 3) & 0x70);
            CP16(sb + sw, Ap + (size_t)r * K + j * 8);
        }
        #pragma unroll
        for (int i = 0; i < 4; i++) {
            int id = tid + i * 256;
            int r = id >> 3, j = id & 7;
            uint32_t off = (uint32_t)(r * 128 + j * 16);
            uint32_t sw = off ^ ((off >> 3) & 0x70);
            CP16(sb + 8192 + sw, Bp + (size_t)r * K + j * 8);
        }
    };

    float acc[2][4][4];
    #pragma unroll
    for (int mi = 0; mi < 2; mi++)
        #pragma unroll
        for (int ni = 0; ni < 4; ni++)
            #pragma unroll
            for (int qq = 0; qq < 4; qq++)
                acc[mi][ni][qq] = 0.0f;

    load_chunk(0); CP_COMMIT();
    load_chunk(1); CP_COMMIT();

    int a_row = wm * 32 + (lane & 15);
    int a_kc  = (lane >> 4);
    int b_row = wn * 32 + (lane & 7) + ((lane >> 4) & 1) * 8;
    int b_kc  = (lane >> 3) & 1;

    for (int c = 0; c < NC; c++) {
        if (c + 1 < NC) { CP_WAIT(1); } else { CP_WAIT(0); }   // last chunk must be fully arrived
        __syncthreads();
        uint32_t sa = base + (c % 3) * GT_STAGE;
        uint32_t sbb = sa + 8192;

        #pragma unroll
        for (int ks = 0; ks < 4; ks++) {
            uint32_t af[2][4];
            #pragma unroll
            for (int mi = 0; mi < 2; mi++) {
                int row = a_row + mi * 16;
                int kc = ks * 2 + a_kc;
                LDSM4(af[mi], sa + row * 128 + ((kc ^ (row & 7)) * 16));
            }
            uint32_t bf[2][4];
            #pragma unroll
            for (int nj = 0; nj < 2; nj++) {
                int row = b_row + nj * 16;
                int kc = ks * 2 + b_kc;
                LDSM4(bf[nj], sbb + row * 128 + ((kc ^ (row & 7)) * 16));
            }
            #pragma unroll
            for (int mi = 0; mi < 2; mi++)
                #pragma unroll
                for (int ni = 0; ni < 4; ni++)
                    mma16816(acc[mi][ni], af[mi], bf[ni >> 1][(ni & 1) * 2],
                             bf[ni >> 1][(ni & 1) * 2 + 1]);
        }
        if (c + 2 < NC) { load_chunk(c + 2); CP_COMMIT(); }
        __syncthreads();
    }

    int erow = bm * 64 + wm * 32 + (lane >> 2);
    int ecol = bn * 128 + wn * 32 + (lane & 3) * 2;
    #pragma unroll
    for (int mi = 0; mi < 2; mi++) {
        #pragma unroll
        for (int ni = 0; ni < 4; ni++) {
            int r0 = erow + mi * 16, r1 = r0 + 8;
            int col = ecol + ni * 8;
            float b0 = 0.0f, b1 = 0.0f;
            if (a.bias) { b0 = a.bias[col]; b1 = a.bias[col + 1]; }
            float v0 = acc[mi][ni][0] + b0, v1 = acc[mi][ni][1] + b1;
            float v2 = acc[mi][ni][2] + b0, v3 = acc[mi][ni][3] + b1;
            if (a.addrow) {
                const float* t0 = a.addrow + (size_t)(r0 >> 2) * N + col;
                const float* t1 = a.addrow + (size_t)(r1 >> 2) * N + col;
                v0 += t0[0]; v1 += t0[1]; v2 += t1[0]; v3 += t1[1];
            }
            if (a.gelu) { v0 = gelu_tanh(v0); v1 = gelu_tanh(v1);
                          v2 = gelu_tanh(v2); v3 = gelu_tanh(v3); }
            if (a.outb) {
                *(__nv_bfloat162*)(a.outb + (size_t)r0 * N + col) = __floats2bfloat162_rn(v0, v1);
                *(__nv_bfloat162*)(a.outb + (size_t)r1 * N + col) = __floats2bfloat162_rn(v2, v3);
            } else {
                *(float2*)(a.outf + (size_t)r0 * N + col) = make_float2(v0, v1);
                *(float2*)(a.outf + (size_t)r1 * N + col) = make_float2(v2, v3);
            }
        }
    }
}

// plain GEMM launch (coarse MLP, dual workload)
__global__ void __launch_bounds__(GT_THREADS)
gemm_plain(GArgs a0, GArgs a1, int n0) {
    extern __shared__ __align__(16) unsigned char smem_dyn[];
    uint32_t base = (smem_to_u32(smem_dyn) + 1023) & ~1023u;
    GArgs a = ((int)blockIdx.x < n0) ? a0 : a1;
    int cta = ((int)blockIdx.x < n0) ? blockIdx.x : (blockIdx.x - n0);
    gemm_item(a, cta, base, threadIdx.x);
}

// ---------------- persistent post-coarse kernel ----------------
struct PP {
    const float* coarse;
    int* idx;
    const float* emb;
    const float* emb_g;
    const float* emb_b;
    __nv_bfloat16* e;
    GArgs g1, g2, g3;
    const float* fine;
    float* out;
};

__device__ __forceinline__ void do_topk(const PP& p, int item, int warp, int lane) {
    int row = item * 8 + warp;
    const float* cr = p.coarse + (size_t)row * N_SZ;
    float4 a = ((const float4*)cr)[lane * 2];
    float4 b = ((const float4*)cr)[lane * 2 + 1];
    float v[8] = {a.x, a.y, a.z, a.w, b.x, b.y, b.z, b.w};
    int base = lane * 8;
    #pragma unroll
    for (int k = 0; k < K_TOP; k++) {
        float bv = v[0]; int bi = 0;
        #pragma unroll
        for (int j = 1; j < 8; j++) if (v[j] > bv) { bv = v[j]; bi = j; }
        int bcol = base + bi;
        #pragma unroll
        for (int o = 16; o; o >>= 1) {
            float ov = __shfl_down_sync(0xffffffffu, bv, o);
            int   oc = __shfl_down_sync(0xffffffffu, bcol, o);
            if (ov > bv || (ov == bv && oc < bcol)) { bv = ov; bcol = oc; }
        }
        bcol = __shfl_sync(0xffffffffu, bcol, 0);
        if (lane == 0) p.idx[row * K_TOP + k] = bcol;
        if (bcol >= base && bcol < base + 8) v[bcol - base] = -INFINITY;
    }
}

__device__ __forceinline__ void do_emb(const PP& p, int item, int warp, int lane) {
    int r = item * 8 + warp;                     // (b,k) row
    int n = p.idx[r];
    const float4* er = (const float4*)(p.emb + (size_t)n * C_SZ);   // 128 float4
    float4 v[4];
    float s = 0.0f, sq = 0.0f;
    #pragma unroll
    for (int j = 0; j < 4; j++) {
        v[j] = er[lane + 32 * j];
        s  += v[j].x + v[j].y + v[j].z + v[j].w;
        sq += v[j].x * v[j].x + v[j].y * v[j].y + v[j].z * v[j].z + v[j].w * v[j].w;
    }
    s = warp_sum(s); sq = warp_sum(sq);
    float mean = s * (1.0f / C_SZ);
    float var  = sq * (1.0f / C_SZ) - mean * mean;
    float rstd = rsqrtf(var + 1e-5f);
    __nv_bfloat16* eo = p.e + (size_t)r * C_SZ;
    #pragma unroll
    for (int j = 0; j < 4; j++) {
        float4 gg = ((const float4*)p.emb_g)[lane + 32 * j];
        float4 bb = ((const float4*)p.emb_b)[lane + 32 * j];
        float y0 = (v[j].x - mean) * rstd * gg.x + bb.x;
        float y1 = (v[j].y - mean) * rstd * gg.y + bb.y;
        float y2 = (v[j].z - mean) * rstd * gg.z + bb.z;
        float y3 = (v[j].w - mean) * rstd * gg.w + bb.w;
        __nv_bfloat162* wp = (__nv_bfloat162*)(eo + (lane + 32 * j) * 4);
        wp[0] = __floats2bfloat162_rn(y0, y1);
        wp[1] = __floats2bfloat162_rn(y2, y3);
    }
}

__device__ __forceinline__ void do_fill(const PP& p, int tile, float* fbase, int tid) {
    int b = tile >> 2;
    int ch0_0 = (tile & 3) * 4;
    if (tid < 64) fbase[tid] = p.coarse[(size_t)b * N_SZ + ch0_0 * 16 + tid] - LOG_F;
    __syncthreads();
    #pragma unroll
    for (int cc = 0; cc < 4; cc++) {
        const float* bs = fbase + cc * 16;
        size_t obase = (size_t)b * 65537 + 1 + (size_t)(ch0_0 + cc) * 4096;
        int head = (int)((4 - (obase & 3)) & 3);
        int nvec = (4096 - head) >> 2;
        int tail = 4096 - head - nvec * 4;
        for (int i = tid; i < nvec; i += 256) {
            int p0 = head + i * 4;
            float4 w;
            float* wp = &w.x;
            #pragma unroll
            for (int u = 0; u < 4; u++)
                wp[u] = bs[((p0 + u) >> 4) & 15];
            __stcs((float4*)(p.out + obase + p0), w);
        }
        int pp = -1;
        if (tid < head) pp = tid;
        else if (tid - head < tail) pp = head + nvec * 4 + (tid - head);
        if (pp >= 0) p.out[obase + pp] = bs[(pp >> 4) & 15];
    }
    __syncthreads();
}

__device__ __forceinline__ void do_scatter(const PP& p, int item, int warp, int lane) {
    int r = item * 8 + warp;
    int b = r >> 2;
    int n = p.idx[r];
    const float4* fr = (const float4*)(p.fine + (size_t)r * F_SZ);
    float4 a = fr[lane * 2], c = fr[lane * 2 + 1];
    float v[8] = {a.x, a.y, a.z, a.w, c.x, c.y, c.z, c.w};
    float m = v[0];
    #pragma unroll
    for (int j = 1; j < 8; j++) m = fmaxf(m, v[j]);
    m = warp_max(m);
    float s = 0.0f;
    #pragma unroll
    for (int j = 0; j < 8; j++) s += expf(v[j] - m);
    s = warp_sum(s);
    float add = p.coarse[(size_t)b * N_SZ + n] - m - logf(s);
    int ch0 = n >> 4, ch1 = n & 15;
    size_t obase = (size_t)b * 65537 + 1 + (size_t)ch0 * 4096 + ch1 * 16;
    #pragma unroll
    for (int q = 0; q < 8; q++) {
        int j = lane * 8 + q;
        p.out[obase + (size_t)(j >> 4) * 256 + (j & 15)] = v[q] + add;
    }
}

#define P_GRID 444

__global__ void __launch_bounds__(GT_THREADS, 3)
persist_kernel(PP p) {
    extern __shared__ __align__(16) unsigned char smem_dyn[];
    uint32_t base = (smem_to_u32(smem_dyn) + 1023) & ~1023u;
    __shared__ int s_it, s_flag;
    __shared__ float s_fbase[64];
    int tid = threadIdx.x, warp = tid >> 5, lane = tid & 31;

    auto POP = [&](int ph) -> int {
        __syncthreads();
        if (tid == 0) s_it = atomicAdd(&g_tick[ph], 1);
        __syncthreads();
        return s_it;
    };
    auto DONE = [&](int ph) {
        __syncthreads();
        if (tid == 0) { __threadfence(); atomicAdd(&g_done[ph], 1); }
    };
    auto WAITD = [&](int ph, int cnt) {
        for (;;) {
            __syncthreads();
            if (tid == 0) {
                if (atomicAdd(&g_done[ph], 0) >= cnt) { s_flag = 1; s_it = -1; }
                else {
                    s_flag = 0;
                    int ft = atomicAdd(&g_tick[PH_FILL], 1);
                    s_it = (ft < CNT_FILL) ? ft : -1;
                }
            }
            __syncthreads();
            if (s_flag) { if (tid == 0) __threadfence(); __syncthreads(); return; }
            if (s_it >= 0) { do_fill(p, s_it, s_fbase, tid); DONE(PH_FILL); }
            else __nanosleep(256);
        }
    };

    // phase 0: top-4
    for (;;) { int t = POP(PH_TOPK); if (t >= CNT_TOPK) break; do_topk(p, t, warp, lane); DONE(PH_TOPK); }
    WAITD(PH_TOPK, CNT_TOPK);
    // phase 1: emb gather + LN
    for (;;) { int t = POP(PH_EMB); if (t >= CNT_EMB) break; do_emb(p, t, warp, lane); DONE(PH_EMB); }
    WAITD(PH_EMB, CNT_EMB);
    // phases 2-4: fine GEMMs
    #pragma unroll 1
    for (int ph = PH_G1; ph <= PH_G3; ph++) {
        GArgs ga = (ph == PH_G1) ? p.g1 : ((ph == PH_G2) ? p.g2 : p.g3);
        int cnt = (ph == PH_G3) ? CNT_G3 : CNT_G1;
        for (;;) { int t = POP(ph); if (t >= cnt) break; gemm_item(ga, t, base, tid); DONE(ph); }
        WAITD(ph, cnt);
    }
    // drain + wait all fill
    WAITD(PH_FILL, CNT_FILL);
    // phase 6: log-softmax scatter (overwrites top-k cells)
    for (;;) { int t = POP(PH_SCAT); if (t >= CNT_SCAT) break; do_scatter(p, t, warp, lane); DONE(PH_SCAT); }
}

// ---------------- launch ----------------
extern "C" void kernel_launch(void* const* d_in, const int* in_sizes, int n_in,
                              void* d_out, int out_size) {
    const float* x     = (const float*)d_in[0];
    const float* in_g  = (const float*)d_in[1];
    const float* in_b  = (const float*)d_in[2];
    const float* nop_w = (const float*)d_in[3];
    const float* nop_b = (const float*)d_in[4];
    const float* c_w1  = (const float*)d_in[5];
    const float* c_b1  = (const float*)d_in[6];
    const float* c_w2  = (const float*)d_in[7];
    const float* c_b2  = (const float*)d_in[8];
    const float* c_w3  = (const float*)d_in[9];
    const float* c_b3  = (const float*)d_in[10];
    const float* emb   = (const float*)d_in[11];
    const float* emb_g = (const float*)d_in[12];
    const float* emb_b = (const float*)d_in[13];
    const float* f_w1  = (const float*)d_in[14];
    const float* f_b1  = (const float*)d_in[15];
    const float* f_w2  = (const float*)d_in[16];
    const float* f_b2  = (const float*)d_in[17];
    const float* f_w3  = (const float*)d_in[18];
    const float* f_b3  = (const float*)d_in[19];
    float* out = (float*)d_out;

    __nv_bfloat16 *xn, *h1, *h2, *e, *g1, *g2, *wbf;
    float *coarse, *fine, *t1;
    int *idx;
    cudaGetSymbolAddress((void**)&xn,     g_xn);
    cudaGetSymbolAddress((void**)&h1,     g_h1);
    cudaGetSymbolAddress((void**)&h2,     g_h2);
    cudaGetSymbolAddress((void**)&coarse, g_coarse);
    cudaGetSymbolAddress((void**)&idx,    g_topidx);
    cudaGetSymbolAddress((void**)&t1,     g_t1);
    cudaGetSymbolAddress((void**)&e,      g_e);
    cudaGetSymbolAddress((void**)&g1,     g_g1);
    cudaGetSymbolAddress((void**)&g2,     g_g2);
    cudaGetSymbolAddress((void**)&fine,   g_fine);
    cudaGetSymbolAddress((void**)&wbf,    g_wbf);

    cudaFuncSetAttribute(gemm_plain, cudaFuncAttributeMaxDynamicSharedMemorySize, GT_SMEM);
    cudaFuncSetAttribute(persist_kernel, cudaFuncAttributeMaxDynamicSharedMemorySize, GT_SMEM);

    // reset work-queue counters (must precede persist_kernel; stream-ordered)
    zero_ctrs<<<1, 32>>>();

    // merged weight transpose+convert
    {
        CvtArgs ca;
        const float*   srcs[7] = {c_w1, c_w2, c_w3, f_w1, f_w1 + 512 * 512, f_w2, f_w3};
        __nv_bfloat16* dsts[7] = {wbf + W_CW1, wbf + W_CW2, wbf + W_CW3, wbf + W_FW1A,
                                  wbf + W_FW1B, wbf + W_FW2, wbf + W_FW3};
        int Ks[7] = {512, 512, 512, 512, 512, 512, 512};
        int Ns[7] = {512, 512, 256, 512, 512, 512, 256};
        int st = 0;
        for (int s = 0; s < 7; s++) {
            ca.W[s] = srcs[s]; ca.Wt[s] = dsts[s]; ca.K[s] = Ks[s]; ca.N[s] = Ns[s];
            ca.start[s] = st;
            st += (Ks[s] >> 5) * (Ns[s] >> 5);
        }
        cvtT_multi<<<st, dim3(32, 8)>>>(ca);
    }

    // LN + no_op head
    ln_noop_kernel<<<B_SZ, 128>>>(x, in_g, in_b, nop_w, nop_b, xn, out);

    GArgs Z = {};
    // coarse GEMM1 + t1 (pair launch)
    {
        GArgs a0 = Z, a1 = Z;
        a0.A = xn; a0.Bw = wbf + W_CW1; a0.bias = c_b1; a0.outb = h1;
        a0.K = 512; a0.N = 512; a0.gridn = 4; a0.gelu = 1;
        a1.A = xn; a1.Bw = wbf + W_FW1A; a1.outf = t1;
        a1.K = 512; a1.N = 512; a1.gridn = 4; a1.gelu = 0;
        gemm_plain<<<256, GT_THREADS, GT_SMEM>>>(a0, a1, 128);
    }
    // coarse GEMM2
    {
        GArgs a = Z;
        a.A = h1; a.Bw = wbf + W_CW2; a.bias = c_b2; a.outb = h2;
        a.K = 512; a.N = 512; a.gridn = 4; a.gelu = 1;
        gemm_plain<<<128, GT_THREADS, GT_SMEM>>>(a, a, 128);
    }
    // coarse GEMM3 -> coarse (fp32)
    {
        GArgs a = Z;
        a.A = h2; a.Bw = wbf + W_CW3; a.bias = c_b3; a.outf = coarse;
        a.K = 512; a.N = 256; a.gridn = 2; a.gelu = 0;
        gemm_plain<<<64, GT_THREADS, GT_SMEM>>>(a, a, 64);
    }

    // persistent post-coarse kernel: topk -> embLN -> fine MLP -> fill -> scatter,
    // with fill tiles drained opportunistically during all waits
    PP pp;
    pp.coarse = coarse; pp.idx = idx; pp.emb = emb; pp.emb_g = emb_g; pp.emb_b = emb_b;
    pp.e = e; pp.fine = fine; pp.out = out;
    pp.g1 = Z;
    pp.g1.A = e;  pp.g1.Bw = wbf + W_FW1B; pp.g1.bias = f_b1; pp.g1.addrow = t1;
    pp.g1.outb = g1; pp.g1.K = 512; pp.g1.N = 512; pp.g1.gridn = 4; pp.g1.gelu = 1;
    pp.g2 = Z;
    pp.g2.A = g1; pp.g2.Bw = wbf + W_FW2;  pp.g2.bias = f_b2;
    pp.g2.outb = g2; pp.g2.K = 512; pp.g2.N = 512; pp.g2.gridn = 4; pp.g2.gelu = 1;
    pp.g3 = Z;
    pp.g3.A = g2; pp.g3.Bw = wbf + W_FW3;  pp.g3.bias = f_b3;
    pp.g3.outf = fine; pp.g3.K = 512; pp.g3.N = 256; pp.g3.gridn = 2; pp.g3.gelu = 0;

    persist_kernel<<<P_GRID, GT_THREADS, GT_SMEM>>>(pp);
}

// round 10
// speedup vs baseline: 1.0704x; 1.0704x over previous
#include <cuda_runtime.h>
#include <cuda_bf16.h>
#include <math.h>
#include <stdint.h>

#define B_SZ   2048
#define C_SZ   512
#define N_SZ   256
#define F_SZ   256
#define K_TOP  4
#define LOG_F  5.545177444479562f

// ---------------- scratch (static device memory; no allocation) ----------------
__device__ __align__(16) __nv_bfloat16 g_xn  [B_SZ * C_SZ];
__device__ __align__(16) __nv_bfloat16 g_h1  [B_SZ * C_SZ];
__device__ __align__(16) __nv_bfloat16 g_h2  [B_SZ * C_SZ];
__device__ __align__(16) float         g_coarse[B_SZ * N_SZ];
__device__ __align__(16) int           g_topidx[B_SZ * K_TOP];
__device__ __align__(16) float         g_t1  [B_SZ * C_SZ];            // xn @ f_w1[:512]
__device__ __align__(16) __nv_bfloat16 g_e   [B_SZ * K_TOP * C_SZ];    // LN(emb[idx])
__device__ __align__(16) __nv_bfloat16 g_g1  [B_SZ * K_TOP * C_SZ];
__device__ __align__(16) __nv_bfloat16 g_g2  [B_SZ * K_TOP * C_SZ];
__device__ __align__(16) float         g_fine[B_SZ * K_TOP * F_SZ];
__device__ __align__(16) __nv_bfloat16 g_wbf [1572864];   // all weights, [N][K] bf16

// weight offsets in g_wbf
#define W_CW1  0
#define W_CW2  262144
#define W_CW3  524288
#define W_FW1A 655360
#define W_FW1B 917504
#define W_FW2  1179648
#define W_FW3  1441792

// ---------------- PTX helpers ----------------
__device__ __forceinline__ uint32_t smem_to_u32(const void* p) {
    uint32_t a;
    asm("{ .reg .u64 t; cvta.to.shared.u64 t, %1; cvt.u32.u64 %0, t; }" : "=r"(a) : "l"(p));
    return a;
}
#define CP16(dst, src)    asm volatile("cp.async.cg.shared.global [%0], [%1], 16;" :: "r"(dst), "l"(src))
#define CP_COMMIT()       asm volatile("cp.async.commit_group;" ::: "memory")
#define CP_WAIT(n)        asm volatile("cp.async.wait_group %0;" :: "n"(n) : "memory")

#define LDSM4(r, addr)                                                           \
    asm volatile("ldmatrix.sync.aligned.m8n8.x4.shared.b16 {%0,%1,%2,%3}, [%4];" \
        : "=r"((r)[0]), "=r"((r)[1]), "=r"((r)[2]), "=r"((r)[3]) : "r"(addr))

__device__ __forceinline__ void mma16816(float* d, const uint32_t* a,
                                         uint32_t b0, uint32_t b1) {
    asm volatile("mma.sync.aligned.m16n8k16.row.col.f32.bf16.bf16.f32 "
        "{%0,%1,%2,%3}, {%4,%5,%6,%7}, {%8,%9}, {%0,%1,%2,%3};"
        : "+f"(d[0]), "+f"(d[1]), "+f"(d[2]), "+f"(d[3])
        : "r"(a[0]), "r"(a[1]), "r"(a[2]), "r"(a[3]), "r"(b0), "r"(b1));
}

// ---------------- misc helpers ----------------
__device__ __forceinline__ float warp_sum(float v) {
    #pragma unroll
    for (int o = 16; o; o >>= 1) v += __shfl_xor_sync(0xffffffffu, v, o);
    return v;
}
__device__ __forceinline__ float warp_max(float v) {
    #pragma unroll
    for (int o = 16; o; o >>= 1) v = fmaxf(v, __shfl_xor_sync(0xffffffffu, v, o));
    return v;
}
__device__ __forceinline__ float gelu_tanh(float x) {
    float x3 = x * x * x;
    return 0.5f * x * (1.0f + tanhf(0.7978845608028654f * (x + 0.044715f * x3)));
}

// ---------------- merged transpose + fp32 -> bf16 over all weights ----------------
struct CvtArgs {
    const float*   W[7];
    __nv_bfloat16* Wt[7];
    int K[7], N[7], start[7];
};
__global__ void cvtT_multi(CvtArgs a) {
    __shared__ float t[32][33];
    int seg = 0;
    #pragma unroll
    for (int s = 1; s < 7; s++) if ((int)blockIdx.x >= a.start[s]) seg = s;
    int tile = blockIdx.x - a.start[seg];
    int K = a.K[seg], N = a.N[seg];
    int ntx = N >> 5;
    int n0 = (tile % ntx) * 32, k0 = (tile / ntx) * 32;
    const float* W = a.W[seg];
    __nv_bfloat16* Wt = a.Wt[seg];
    int tx = threadIdx.x, ty = threadIdx.y;
    #pragma unroll
    for (int i = 0; i < 4; i++)
        t[ty + i * 8][tx] = W[(size_t)(k0 + ty + i * 8) * N + n0 + tx];
    __syncthreads();
    #pragma unroll
    for (int i = 0; i < 4; i++)
        Wt[(size_t)(n0 + ty + i * 8) * K + k0 + tx] = __float2bfloat16(t[tx][ty + i * 8]);
}

// ---------------- LayerNorm(x) + no_op head ----------------
__global__ void ln_noop_kernel(const float* __restrict__ x,
                               const float* __restrict__ g, const float* __restrict__ b,
                               const float* __restrict__ nw, const float* __restrict__ nb,
                               __nv_bfloat16* __restrict__ xn, float* __restrict__ out) {
    int row = blockIdx.x, t = threadIdx.x;
    int w = t >> 5, lane = t & 31;
    float4 v = ((const float4*)(x + (size_t)row * C_SZ))[t];

    float s  = v.x + v.y + v.z + v.w;
    float sq = v.x * v.x + v.y * v.y + v.z * v.z + v.w * v.w;

    __shared__ float rs[4], rq[4], rn[4];
    float ws = warp_sum(s), wq = warp_sum(sq);
    if (lane == 0) { rs[w] = ws; rq[w] = wq; }
    __syncthreads();
    float tot_s = rs[0] + rs[1] + rs[2] + rs[3];
    float tot_q = rq[0] + rq[1] + rq[2] + rq[3];
    float mean = tot_s * (1.0f / C_SZ);
    float var  = tot_q * (1.0f / C_SZ) - mean * mean;
    float rstd = rsqrtf(var + 1e-5f);

    float4 gg = ((const float4*)g)[t];
    float4 bb = ((const float4*)b)[t];
    float y0 = (v.x - mean) * rstd * gg.x + bb.x;
    float y1 = (v.y - mean) * rstd * gg.y + bb.y;
    float y2 = (v.z - mean) * rstd * gg.z + bb.z;
    float y3 = (v.w - mean) * rstd * gg.w + bb.w;

    __nv_bfloat16* xr = xn + (size_t)row * C_SZ + t * 4;
    ((__nv_bfloat162*)xr)[0] = __floats2bfloat162_rn(y0, y1);
    ((__nv_bfloat162*)xr)[1] = __floats2bfloat162_rn(y2, y3);

    float4 ww = ((const float4*)nw)[t];
    float acc = y0 * ww.x + y1 * ww.y + y2 * ww.z + y3 * ww.w;
    float wacc = warp_sum(acc);
    if (lane == 0) rn[w] = wacc;
    __syncthreads();
    if (t == 0) out[(size_t)row * 65537] = rn[0] + rn[1] + rn[2] + rn[3] + nb[0];
}

// ---------------- templated mma.sync bf16 GEMM (TM x 128 CTA tile) + appended fill ----
// blocks [0, n0)     : GEMM workload a0
// blocks [n0, nGemm) : GEMM workload a1
// blocks [nGemm, ..) : broadcast-fill tiles (tileBase + bid - nGemm)
#define GT_THREADS 256

struct GArgs {
    const __nv_bfloat16* A;
    const __nv_bfloat16* Bw;
    const float* bias;      // nullable
    const float* addrow;    // nullable: += addrow[(row>>2)*N + col]
    __nv_bfloat16* outb;    // one of outb/outf non-null
    float* outf;
    int K, N, gridn, gelu;
};
struct FillArgs {
    const float* coarse;    // nullable if no fill blocks
    float* out;
    int tileBase;
};

template<int TM>
__global__ void __launch_bounds__(GT_THREADS)
gemm_mma(GArgs a0, GArgs a1, int n0, int nGemm, FillArgs fa) {
    constexpr int AST = TM * 128;            // A stage bytes
    constexpr int STG = AST + 16384;         // stage bytes (A + B)
    constexpr int MI  = TM / 32;             // m16 blocks per warp

    extern __shared__ __align__(16) unsigned char smem_dyn[];
    int bid = blockIdx.x;
    int tid = threadIdx.x;

    if (bid >= nGemm) {
        // ---- fill workload: 4 ch0 spans of broadcast(coarse - logF) ----
        __shared__ float fbase[64];
        int tile = fa.tileBase + bid - nGemm;
        int b = tile >> 2;
        int ch0_0 = (tile & 3) * 4;
        if (tid < 64) fbase[tid] = fa.coarse[(size_t)b * N_SZ + ch0_0 * 16 + tid] - LOG_F;
        __syncthreads();
        #pragma unroll
        for (int cc = 0; cc < 4; cc++) {
            const float* bs = fbase + cc * 16;
            size_t obase = (size_t)b * 65537 + 1 + (size_t)(ch0_0 + cc) * 4096;
            int head = (int)((4 - (obase & 3)) & 3);
            int nvec = (4096 - head) >> 2;
            int tail = 4096 - head - nvec * 4;
            for (int i = tid; i < nvec; i += 256) {
                int p0 = head + i * 4;
                float4 w;
                float* wp = &w.x;
                #pragma unroll
                for (int u = 0; u < 4; u++)
                    wp[u] = bs[((p0 + u) >> 4) & 15];
                __stcs((float4*)(fa.out + obase + p0), w);
            }
            int p = -1;
            if (tid < head) p = tid;
            else if (tid - head < tail) p = head + nvec * 4 + (tid - head);
            if (p >= 0) fa.out[obase + p] = bs[(p >> 4) & 15];
        }
        return;
    }

    uint32_t base = (smem_to_u32(smem_dyn) + 1023) & ~1023u;
    GArgs a = (bid < n0) ? a0 : a1;
    int cta = (bid < n0) ? bid : (bid - n0);
    int bm = cta / a.gridn, bn = cta % a.gridn;
    const int K = a.K, N = a.N;
    const int NC = K >> 6;

    int warp = tid >> 5, lane = tid & 31;
    int wm = warp >> 2, wn = warp & 3;

    auto load_chunk = [&](int c) {
        uint32_t sb = base + (c % 3) * STG;
        const __nv_bfloat16* Ap = a.A  + (size_t)bm * TM * K + (size_t)c * 64;
        const __nv_bfloat16* Bp = a.Bw + (size_t)bn * 128 * K + (size_t)c * 64;
        #pragma unroll
        for (int i = 0; i < MI; i++) {
            int id = tid + i * 256;
            int r = id >> 3, j = id & 7;
            uint32_t off = (uint32_t)(r * 128 + j * 16);
            uint32_t sw = off ^ ((off >> 3) & 0x70);
            CP16(sb + sw, Ap + (size_t)r * K + j * 8);
        }
        #pragma unroll
        for (int i = 0; i < 4; i++) {
            int id = tid + i * 256;
            int r = id >> 3, j = id & 7;
            uint32_t off = (uint32_t)(r * 128 + j * 16);
            uint32_t sw = off ^ ((off >> 3) & 0x70);
            CP16(sb + AST + sw, Bp + (size_t)r * K + j * 8);
        }
    };

    float acc[MI][4][4];
    #pragma unroll
    for (int mi = 0; mi < MI; mi++)
        #pragma unroll
        for (int ni = 0; ni < 4; ni++)
            #pragma unroll
            for (int q = 0; q < 4; q++)
                acc[mi][ni][q] = 0.0f;

    load_chunk(0); CP_COMMIT();
    load_chunk(1); CP_COMMIT();

    int a_row = wm * (TM / 2) + (lane & 15);
    int a_kc  = (lane >> 4);
    int b_row = wn * 32 + (lane & 7) + ((lane >> 4) & 1) * 8;
    int b_kc  = (lane >> 3) & 1;

    for (int c = 0; c < NC; c++) {
        if (c + 1 < NC) { CP_WAIT(1); } else { CP_WAIT(0); }
        __syncthreads();
        uint32_t sa = base + (c % 3) * STG;
        uint32_t sbb = sa + AST;

        #pragma unroll
        for (int ks = 0; ks < 4; ks++) {
            uint32_t af[MI][4];
            #pragma unroll
            for (int mi = 0; mi < MI; mi++) {
                int row = a_row + mi * 16;
                int kc = ks * 2 + a_kc;
                LDSM4(af[mi], sa + row * 128 + ((kc ^ (row & 7)) * 16));
            }
            uint32_t bf[2][4];
            #pragma unroll
            for (int nj = 0; nj < 2; nj++) {
                int row = b_row + nj * 16;
                int kc = ks * 2 + b_kc;
                LDSM4(bf[nj], sbb + row * 128 + ((kc ^ (row & 7)) * 16));
            }
            #pragma unroll
            for (int mi = 0; mi < MI; mi++)
                #pragma unroll
                for (int ni = 0; ni < 4; ni++)
                    mma16816(acc[mi][ni], af[mi], bf[ni >> 1][(ni & 1) * 2],
                             bf[ni >> 1][(ni & 1) * 2 + 1]);
        }
        if (c + 2 < NC) { load_chunk(c + 2); CP_COMMIT(); }
        __syncthreads();
    }

    // epilogue: bias (+ addrow) + act, straight from registers
    int erow = bm * TM + wm * (TM / 2) + (lane >> 2);
    int ecol = bn * 128 + wn * 32 + (lane & 3) * 2;
    #pragma unroll
    for (int mi = 0; mi < MI; mi++) {
        #pragma unroll
        for (int ni = 0; ni < 4; ni++) {
            int r0 = erow + mi * 16, r1 = r0 + 8;
            int col = ecol + ni * 8;
            float b0 = 0.0f, b1 = 0.0f;
            if (a.bias) { b0 = a.bias[col]; b1 = a.bias[col + 1]; }
            float v0 = acc[mi][ni][0] + b0, v1 = acc[mi][ni][1] + b1;
            float v2 = acc[mi][ni][2] + b0, v3 = acc[mi][ni][3] + b1;
            if (a.addrow) {
                const float* t0 = a.addrow + (size_t)(r0 >> 2) * N + col;
                const float* t1 = a.addrow + (size_t)(r1 >> 2) * N + col;
                v0 += t0[0]; v1 += t0[1]; v2 += t1[0]; v3 += t1[1];
            }
            if (a.gelu) { v0 = gelu_tanh(v0); v1 = gelu_tanh(v1);
                          v2 = gelu_tanh(v2); v3 = gelu_tanh(v3); }
            if (a.outb) {
                *(__nv_bfloat162*)(a.outb + (size_t)r0 * N + col) = __floats2bfloat162_rn(v0, v1);
                *(__nv_bfloat162*)(a.outb + (size_t)r1 * N + col) = __floats2bfloat162_rn(v2, v3);
            } else {
                *(float2*)(a.outf + (size_t)r0 * N + col) = make_float2(v0, v1);
                *(float2*)(a.outf + (size_t)r1 * N + col) = make_float2(v2, v3);
            }
        }
    }
}

// ---------------- top-4 per row (one warp per row) ----------------
__global__ void topk_kernel(const float* __restrict__ coarse, int* __restrict__ idx) {
    int warp = threadIdx.x >> 5, lane = threadIdx.x & 31;
    int row = blockIdx.x * 8 + warp;
    const float* cr = coarse + (size_t)row * N_SZ;
    float4 a = ((const float4*)cr)[lane * 2];
    float4 b = ((const float4*)cr)[lane * 2 + 1];
    float v[8] = {a.x, a.y, a.z, a.w, b.x, b.y, b.z, b.w};
    int base = lane * 8;
    #pragma unroll
    for (int k = 0; k < K_TOP; k++) {
        float bv = v[0]; int bi = 0;
        #pragma unroll
        for (int j = 1; j < 8; j++) if (v[j] > bv) { bv = v[j]; bi = j; }
        int bcol = base + bi;
        #pragma unroll
        for (int o = 16; o; o >>= 1) {
            float ov = __shfl_down_sync(0xffffffffu, bv, o);
            int   oc = __shfl_down_sync(0xffffffffu, bcol, o);
            if (ov > bv || (ov == bv && oc < bcol)) { bv = ov; bcol = oc; }
        }
        bcol = __shfl_sync(0xffffffffu, bcol, 0);
        if (lane == 0) idx[row * K_TOP + k] = bcol;
        if (bcol >= base && bcol < base + 8) v[bcol - base] = -INFINITY;
    }
}

// ---------------- gather emb[idx], LN -> e (bf16) ----------------
__global__ void embcat_kernel(const int* __restrict__ idx, const float* __restrict__ emb,
                              const float* __restrict__ g, const float* __restrict__ b,
                              __nv_bfloat16* __restrict__ e) {
    int r = blockIdx.x, t = threadIdx.x;         // 128 threads
    int w = t >> 5, lane = t & 31;
    int n = idx[r];

    float4 v = ((const float4*)(emb + (size_t)n * C_SZ))[t];
    float s  = v.x + v.y + v.z + v.w;
    float sq = v.x * v.x + v.y * v.y + v.z * v.z + v.w * v.w;
    __shared__ float rs[4], rq[4];
    float ws = warp_sum(s), wq = warp_sum(sq);
    if (lane == 0) { rs[w] = ws; rq[w] = wq; }
    __syncthreads();
    float tot_s = rs[0] + rs[1] + rs[2] + rs[3];
    float tot_q = rq[0] + rq[1] + rq[2] + rq[3];
    float mean = tot_s * (1.0f / C_SZ);
    float var  = tot_q * (1.0f / C_SZ) - mean * mean;
    float rstd = rsqrtf(var + 1e-5f);

    float4 gg = ((const float4*)g)[t];
    float4 bb = ((const float4*)b)[t];
    float y0 = (v.x - mean) * rstd * gg.x + bb.x;
    float y1 = (v.y - mean) * rstd * gg.y + bb.y;
    float y2 = (v.z - mean) * rstd * gg.z + bb.z;
    float y3 = (v.w - mean) * rstd * gg.w + bb.w;
    __nv_bfloat16* fr = e + (size_t)r * C_SZ + t * 4;
    ((__nv_bfloat162*)fr)[0] = __floats2bfloat162_rn(y0, y1);
    ((__nv_bfloat162*)fr)[1] = __floats2bfloat162_rn(y2, y3);
}

// ---------------- fused log-softmax + scatter of top-k cells into out ----------------
__global__ void scatter_vals(const float* __restrict__ fine, const float* __restrict__ coarse,
                             const int* __restrict__ idx, float* __restrict__ out) {
    int warp = threadIdx.x >> 5, lane = threadIdx.x & 31;
    int r = blockIdx.x * 8 + warp;           // (b, k) row in [0, 8192)
    int b = r >> 2;
    int n = idx[r];
    const float4* fr = (const float4*)(fine + (size_t)r * F_SZ);
    float4 a = fr[lane * 2], c = fr[lane * 2 + 1];
    float v[8] = {a.x, a.y, a.z, a.w, c.x, c.y, c.z, c.w};
    float m = v[0];
    #pragma unroll
    for (int j = 1; j < 8; j++) m = fmaxf(m, v[j]);
    m = warp_max(m);
    float s = 0.0f;
    #pragma unroll
    for (int j = 0; j < 8; j++) s += expf(v[j] - m);
    s = warp_sum(s);
    float add = coarse[(size_t)b * N_SZ + n] - m - logf(s);

    int ch0 = n >> 4, ch1 = n & 15;
    size_t obase = (size_t)b * 65537 + 1 + (size_t)ch0 * 4096 + ch1 * 16;
    #pragma unroll
    for (int q = 0; q < 8; q++) {
        int j = lane * 8 + q;                 // fine element: fh0 = j>>4, fh1 = j&15
        out[obase + (size_t)(j >> 4) * 256 + (j & 15)] = v[q] + add;
    }
}

// ---------------- launch ----------------
extern "C" void kernel_launch(void* const* d_in, const int* in_sizes, int n_in,
                              void* d_out, int out_size) {
    const float* x     = (const float*)d_in[0];
    const float* in_g  = (const float*)d_in[1];
    const float* in_b  = (const float*)d_in[2];
    const float* nop_w = (const float*)d_in[3];
    const float* nop_b = (const float*)d_in[4];
    const float* c_w1  = (const float*)d_in[5];
    const float* c_b1  = (const float*)d_in[6];
    const float* c_w2  = (const float*)d_in[7];
    const float* c_b2  = (const float*)d_in[8];
    const float* c_w3  = (const float*)d_in[9];
    const float* c_b3  = (const float*)d_in[10];
    const float* emb   = (const float*)d_in[11];
    const float* emb_g = (const float*)d_in[12];
    const float* emb_b = (const float*)d_in[13];
    const float* f_w1  = (const float*)d_in[14];
    const float* f_b1  = (const float*)d_in[15];
    const float* f_w2  = (const float*)d_in[16];
    const float* f_b2  = (const float*)d_in[17];
    const float* f_w3  = (const float*)d_in[18];
    const float* f_b3  = (const float*)d_in[19];
    float* out = (float*)d_out;

    __nv_bfloat16 *xn, *h1, *h2, *e, *g1, *g2, *wbf;
    float *coarse, *fine, *t1;
    int *idx;
    cudaGetSymbolAddress((void**)&xn,     g_xn);
    cudaGetSymbolAddress((void**)&h1,     g_h1);
    cudaGetSymbolAddress((void**)&h2,     g_h2);
    cudaGetSymbolAddress((void**)&coarse, g_coarse);
    cudaGetSymbolAddress((void**)&idx,    g_topidx);
    cudaGetSymbolAddress((void**)&t1,     g_t1);
    cudaGetSymbolAddress((void**)&e,      g_e);
    cudaGetSymbolAddress((void**)&g1,     g_g1);
    cudaGetSymbolAddress((void**)&g2,     g_g2);
    cudaGetSymbolAddress((void**)&fine,   g_fine);
    cudaGetSymbolAddress((void**)&wbf,    g_wbf);

    const int SMEM32 = 3 * (32 * 128 + 16384) + 1024;   // 62464
    const int SMEM64 = 3 * (64 * 128 + 16384) + 1024;   // 74752
    cudaFuncSetAttribute(gemm_mma<32>, cudaFuncAttributeMaxDynamicSharedMemorySize, SMEM32);
    cudaFuncSetAttribute(gemm_mma<64>, cudaFuncAttributeMaxDynamicSharedMemorySize, SMEM64);

    // merged weight transpose+convert (7 segments of 32x32 tiles)
    {
        CvtArgs ca;
        const float*   srcs[7] = {c_w1, c_w2, c_w3, f_w1, f_w1 + 512 * 512, f_w2, f_w3};
        __nv_bfloat16* dsts[7] = {wbf + W_CW1, wbf + W_CW2, wbf + W_CW3, wbf + W_FW1A,
                                  wbf + W_FW1B, wbf + W_FW2, wbf + W_FW3};
        int Ks[7] = {512, 512, 512, 512, 512, 512, 512};
        int Ns[7] = {512, 512, 256, 512, 512, 512, 256};
        int st = 0;
        for (int s = 0; s < 7; s++) {
            ca.W[s] = srcs[s]; ca.Wt[s] = dsts[s]; ca.K[s] = Ks[s]; ca.N[s] = Ns[s];
            ca.start[s] = st;
            st += (Ks[s] >> 5) * (Ns[s] >> 5);
        }
        cvtT_multi<<<st, dim3(32, 8)>>>(ca);
    }

    // LN + no_op head
    ln_noop_kernel<<<B_SZ, 128>>>(x, in_g, in_b, nop_w, nop_b, xn, out);

    GArgs Z = {};
    FillArgs FZ = {};
    // coarse GEMM1 (256 CTAs, TM=32) + t1 (256 CTAs) in one launch
    {
        GArgs a0 = Z, a1 = Z;
        a0.A = xn; a0.Bw = wbf + W_CW1; a0.bias = c_b1; a0.outb = h1;
        a0.K = 512; a0.N = 512; a0.gridn = 4; a0.gelu = 1;
        a1.A = xn; a1.Bw = wbf + W_FW1A; a1.outf = t1;
        a1.K = 512; a1.N = 512; a1.gridn = 4; a1.gelu = 0;
        gemm_mma<32><<<512, GT_THREADS, SMEM32>>>(a0, a1, 256, 512, FZ);
    }
    // coarse GEMM2 (TM=32, 256 CTAs)
    {
        GArgs a = Z;
        a.A = h1; a.Bw = wbf + W_CW2; a.bias = c_b2; a.outb = h2;
        a.K = 512; a.N = 512; a.gridn = 4; a.gelu = 1;
        gemm_mma<32><<<256, GT_THREADS, SMEM32>>>(a, a, 256, 256, FZ);
    }
    // coarse GEMM3 -> coarse (fp32) (TM=32, 128 CTAs)
    {
        GArgs a = Z;
        a.A = h2; a.Bw = wbf + W_CW3; a.bias = c_b3; a.outf = coarse;
        a.K = 512; a.N = 256; a.gridn = 2; a.gelu = 0;
        gemm_mma<32><<<128, GT_THREADS, SMEM32>>>(a, a, 128, 128, FZ);
    }

    // top-4 + gather/LN
    topk_kernel<<<B_SZ / 8, 256>>>(coarse, idx);
    embcat_kernel<<<B_SZ * K_TOP, 128>>>(idx, emb, emb_g, emb_b, e);

    // fine GEMM1 & GEMM2: pure GEMM launches (TM=64)
    {
        GArgs a = Z;
        a.A = e; a.Bw = wbf + W_FW1B; a.bias = f_b1; a.addrow = t1; a.outb = g1;
        a.K = 512; a.N = 512; a.gridn = 4; a.gelu = 1;
        gemm_mma<64><<<512, GT_THREADS, SMEM64>>>(a, a, 512, 512, FZ);
    }
    {
        GArgs a = Z;
        a.A = g1; a.Bw = wbf + W_FW2; a.bias = f_b2; a.outb = g2;
        a.K = 512; a.N = 512; a.gridn = 4; a.gelu = 1;
        gemm_mma<64><<<512, GT_THREADS, SMEM64>>>(a, a, 512, 512, FZ);
    }
    // fine GEMM3 + ALL 8192 fill tiles in one launch (GEMM blocks first)
    {
        GArgs a = Z;
        a.A = g2; a.Bw = wbf + W_FW3; a.bias = f_b3; a.outf = fine;
        a.K = 512; a.N = 256; a.gridn = 2; a.gelu = 0;
        FillArgs fa = {coarse, out, 0};
        gemm_mma<64><<<256 + 8192, GT_THREADS, SMEM64>>>(a, a, 256, 256, fa);
    }

    // scatter overwrites the top-k cells after fill wrote them (same stream)
    scatter_vals<<<B_SZ * K_TOP / 8, 256>>>(fine, coarse, idx, out);
}

// round 11
// speedup vs baseline: 1.1102x; 1.0371x over previous
#include <cuda_runtime.h>
#include <cuda_bf16.h>
#include <math.h>
#include <stdint.h>

#define B_SZ   2048
#define C_SZ   512
#define N_SZ   256
#define F_SZ   256
#define K_TOP  4
#define LOG_F  5.545177444479562f

// ---------------- scratch (static device memory; no allocation) ----------------
__device__ __align__(16) __nv_bfloat16 g_xn  [B_SZ * C_SZ];
__device__ __align__(16) __nv_bfloat16 g_h1  [B_SZ * C_SZ];
__device__ __align__(16) __nv_bfloat16 g_h2  [B_SZ * C_SZ];
__device__ __align__(16) float         g_coarse[B_SZ * N_SZ];
__device__ __align__(16) int           g_topidx[B_SZ * K_TOP];
__device__ __align__(16) float         g_t1  [B_SZ * C_SZ];
__device__ __align__(16) __nv_bfloat16 g_e   [B_SZ * K_TOP * C_SZ];
__device__ __align__(16) __nv_bfloat16 g_g1  [B_SZ * K_TOP * C_SZ];
__device__ __align__(16) __nv_bfloat16 g_g2  [B_SZ * K_TOP * C_SZ];
__device__ __align__(16) float         g_fine[B_SZ * K_TOP * F_SZ];
__device__ __align__(16) __nv_bfloat16 g_wbf [1572864];

#define W_CW1  0
#define W_CW2  262144
#define W_CW3  524288
#define W_FW1A 655360
#define W_FW1B 917504
#define W_FW2  1179648
#define W_FW3  1441792

// ---------------- PTX helpers ----------------
__device__ __forceinline__ uint32_t smem_to_u32(const void* p) {
    uint32_t a;
    asm("{ .reg .u64 t; cvta.to.shared.u64 t, %1; cvt.u32.u64 %0, t; }" : "=r"(a) : "l"(p));
    return a;
}
#define CP16(dst, src)    asm volatile("cp.async.cg.shared.global [%0], [%1], 16;" :: "r"(dst), "l"(src))
#define CP_COMMIT()       asm volatile("cp.async.commit_group;" ::: "memory")
#define CP_WAIT(n)        asm volatile("cp.async.wait_group %0;" :: "n"(n) : "memory")

#define LDSM4(r, addr)                                                           \
    asm volatile("ldmatrix.sync.aligned.m8n8.x4.shared.b16 {%0,%1,%2,%3}, [%4];" \
        : "=r"((r)[0]), "=r"((r)[1]), "=r"((r)[2]), "=r"((r)[3]) : "r"(addr))

__device__ __forceinline__ void mma16816(float* d, const uint32_t* a,
                                         uint32_t b0, uint32_t b1) {
    asm volatile("mma.sync.aligned.m16n8k16.row.col.f32.bf16.bf16.f32 "
        "{%0,%1,%2,%3}, {%4,%5,%6,%7}, {%8,%9}, {%0,%1,%2,%3};"
        : "+f"(d[0]), "+f"(d[1]), "+f"(d[2]), "+f"(d[3])
        : "r"(a[0]), "r"(a[1]), "r"(a[2]), "r"(a[3]), "r"(b0), "r"(b1));
}

// ---------------- misc helpers ----------------
__device__ __forceinline__ float warp_sum(float v) {
    #pragma unroll
    for (int o = 16; o; o >>= 1) v += __shfl_xor_sync(0xffffffffu, v, o);
    return v;
}
__device__ __forceinline__ float warp_max(float v) {
    #pragma unroll
    for (int o = 16; o; o >>= 1) v = fmaxf(v, __shfl_xor_sync(0xffffffffu, v, o));
    return v;
}
__device__ __forceinline__ float gelu_tanh(float x) {
    float x3 = x * x * x;
    return 0.5f * x * (1.0f + tanhf(0.7978845608028654f * (x + 0.044715f * x3)));
}

// ---------------- fused prep: weight transpose+cvt (blocks 0..1535) + LN (blocks 1536..2559) ----
struct CvtArgs {
    const float*   W[7];
    __nv_bfloat16* Wt[7];
    int K[7], N[7], start[7];
};
__global__ void prep_kernel(CvtArgs a,
                            const float* __restrict__ x,
                            const float* __restrict__ g, const float* __restrict__ b,
                            const float* __restrict__ nw, const float* __restrict__ nb,
                            __nv_bfloat16* __restrict__ xn, float* __restrict__ out) {
    int bid = blockIdx.x, t = threadIdx.x;
    if (bid < 1536) {
        __shared__ float tt[32][33];
        int seg = 0;
        #pragma unroll
        for (int s = 1; s < 7; s++) if (bid >= a.start[s]) seg = s;
        int tile = bid - a.start[seg];
        int K = a.K[seg], N = a.N[seg];
        int ntx = N >> 5;
        int n0 = (tile % ntx) * 32, k0 = (tile / ntx) * 32;
        const float* W = a.W[seg];
        __nv_bfloat16* Wt = a.Wt[seg];
        int tx = t & 31, ty = t >> 5;
        #pragma unroll
        for (int i = 0; i < 4; i++)
            tt[ty + i * 8][tx] = W[(size_t)(k0 + ty + i * 8) * N + n0 + tx];
        __syncthreads();
        #pragma unroll
        for (int i = 0; i < 4; i++)
            Wt[(size_t)(n0 + ty + i * 8) * K + k0 + tx] = __float2bfloat16(tt[tx][ty + i * 8]);
        return;
    }
    // LN + no_op: two rows per block (half-block each)
    __shared__ float rs[2][4], rq[2][4], rn[2][4];
    int half = t >> 7, ht = t & 127;
    int w = (t >> 5) & 3, lane = t & 31;
    int row = (bid - 1536) * 2 + half;
    float4 v = ((const float4*)(x + (size_t)row * C_SZ))[ht];
    float s  = v.x + v.y + v.z + v.w;
    float sq = v.x * v.x + v.y * v.y + v.z * v.z + v.w * v.w;
    float ws = warp_sum(s), wq = warp_sum(sq);
    if (lane == 0) { rs[half][w] = ws; rq[half][w] = wq; }
    __syncthreads();
    float tot_s = rs[half][0] + rs[half][1] + rs[half][2] + rs[half][3];
    float tot_q = rq[half][0] + rq[half][1] + rq[half][2] + rq[half][3];
    float mean = tot_s * (1.0f / C_SZ);
    float var  = tot_q * (1.0f / C_SZ) - mean * mean;
    float rstd = rsqrtf(var + 1e-5f);
    float4 gg = ((const float4*)g)[ht];
    float4 bb = ((const float4*)b)[ht];
    float y0 = (v.x - mean) * rstd * gg.x + bb.x;
    float y1 = (v.y - mean) * rstd * gg.y + bb.y;
    float y2 = (v.z - mean) * rstd * gg.z + bb.z;
    float y3 = (v.w - mean) * rstd * gg.w + bb.w;
    __nv_bfloat16* xr = xn + (size_t)row * C_SZ + ht * 4;
    ((__nv_bfloat162*)xr)[0] = __floats2bfloat162_rn(y0, y1);
    ((__nv_bfloat162*)xr)[1] = __floats2bfloat162_rn(y2, y3);
    float4 ww = ((const float4*)nw)[ht];
    float acc = y0 * ww.x + y1 * ww.y + y2 * ww.z + y3 * ww.w;
    float wacc = warp_sum(acc);
    if (lane == 0) rn[half][w] = wacc;
    __syncthreads();
    if (ht == 0)
        out[(size_t)row * 65537] = rn[half][0] + rn[half][1] + rn[half][2] + rn[half][3] + nb[0];
}

// ---------------- broadcast-fill tile (shared by bg + trailing fill CTAs) ----------------
__device__ __forceinline__ void do_fill_tile(const float* __restrict__ coarse,
                                             float* __restrict__ out,
                                             int tile, float* fbase, int tid) {
    int b = tile >> 2;
    int ch0_0 = (tile & 3) * 4;
    __syncthreads();                       // protect fbase from previous tile readers
    if (tid < 64) fbase[tid] = coarse[(size_t)b * N_SZ + ch0_0 * 16 + tid] - LOG_F;
    __syncthreads();
    #pragma unroll
    for (int cc = 0; cc < 4; cc++) {
        const float* bs = fbase + cc * 16;
        size_t obase = (size_t)b * 65537 + 1 + (size_t)(ch0_0 + cc) * 4096;
        int head = (int)((4 - (obase & 3)) & 3);
        int nvec = (4096 - head) >> 2;
        int tail = 4096 - head - nvec * 4;
        for (int i = tid; i < nvec; i += 256) {
            int p0 = head + i * 4;
            float4 w;
            float* wp = &w.x;
            #pragma unroll
            for (int u = 0; u < 4; u++)
                wp[u] = bs[((p0 + u) >> 4) & 15];
            __stcs((float4*)(out + obase + p0), w);
        }
        int p = -1;
        if (tid < head) p = tid;
        else if (tid - head < tail) p = head + nvec * 4 + (tid - head);
        if (p >= 0) out[obase + p] = bs[(p >> 4) & 15];
    }
}

// ---------------- templated mma.sync bf16 GEMM (TM x 128 tile, NS-stage) + fill CTAs ----
// bids [0, bgCtas)                : background fill, strided tiles [tileBase, tileBase+bgCount)
// q = bid - bgCtas; [0, n0)       : GEMM workload a0
//                   [n0, nGemm)   : GEMM workload a1
//                   [nGemm, ...)  : trailing fill tiles from tileBase+bgCount
#define GT_THREADS 256

struct GArgs {
    const __nv_bfloat16* A;
    const __nv_bfloat16* Bw;
    const float* bias;
    const float* addrow;
    __nv_bfloat16* outb;
    float* outf;
    int K, N, gridn, gelu;
};
struct FillArgs {
    const float* coarse;
    float* out;
    int tileBase, bgCtas, bgCount;
};

template<int TM, int NS>
__global__ void __launch_bounds__(GT_THREADS, (TM == 32 ? 4 : 2))
gemm_mma(GArgs a0, GArgs a1, int n0, int nGemm, FillArgs fa) {
    constexpr int AST = TM * 128;
    constexpr int STG = AST + 16384;
    constexpr int MI  = TM / 32;

    extern __shared__ __align__(16) unsigned char smem_dyn[];
    __shared__ float fbase[64];
    int bid = blockIdx.x;
    int tid = threadIdx.x;

    if (bid < fa.bgCtas) {
        for (int tl = fa.tileBase + bid; tl < fa.tileBase + fa.bgCount; tl += fa.bgCtas)
            do_fill_tile(fa.coarse, fa.out, tl, fbase, tid);
        return;
    }
    int q = bid - fa.bgCtas;
    if (q >= nGemm) {
        do_fill_tile(fa.coarse, fa.out, fa.tileBase + fa.bgCount + (q - nGemm), fbase, tid);
        return;
    }

    uint32_t base = (smem_to_u32(smem_dyn) + 1023) & ~1023u;
    GArgs a = (q < n0) ? a0 : a1;
    int cta = (q < n0) ? q : (q - n0);
    int bm = cta / a.gridn, bn = cta % a.gridn;
    const int K = a.K, N = a.N;
    const int NC = K >> 6;

    int warp = tid >> 5, lane = tid & 31;
    int wm = warp >> 2, wn = warp & 3;

    auto load_chunk = [&](int c) {
        uint32_t sb = base + (c % NS) * STG;
        const __nv_bfloat16* Ap = a.A  + (size_t)bm * TM * K + (size_t)c * 64;
        const __nv_bfloat16* Bp = a.Bw + (size_t)bn * 128 * K + (size_t)c * 64;
        #pragma unroll
        for (int i = 0; i < MI; i++) {
            int id = tid + i * 256;
            int r = id >> 3, j = id & 7;
            uint32_t off = (uint32_t)(r * 128 + j * 16);
            uint32_t sw = off ^ ((off >> 3) & 0x70);
            CP16(sb + sw, Ap + (size_t)r * K + j * 8);
        }
        #pragma unroll
        for (int i = 0; i < 4; i++) {
            int id = tid + i * 256;
            int r = id >> 3, j = id & 7;
            uint32_t off = (uint32_t)(r * 128 + j * 16);
            uint32_t sw = off ^ ((off >> 3) & 0x70);
            CP16(sb + AST + sw, Bp + (size_t)r * K + j * 8);
        }
    };

    float acc[MI][4][4];
    #pragma unroll
    for (int mi = 0; mi < MI; mi++)
        #pragma unroll
        for (int ni = 0; ni < 4; ni++)
            #pragma unroll
            for (int qq = 0; qq < 4; qq++)
                acc[mi][ni][qq] = 0.0f;

    load_chunk(0); CP_COMMIT();
    load_chunk(1); CP_COMMIT();

    int a_row = wm * (TM / 2) + (lane & 15);
    int a_kc  = (lane >> 4);
    int b_row = wn * 32 + (lane & 7) + ((lane >> 4) & 1) * 8;
    int b_kc  = (lane >> 3) & 1;

    for (int c = 0; c < NC; c++) {
        if (c + 1 < NC) { CP_WAIT(1); } else { CP_WAIT(0); }
        __syncthreads();
        uint32_t sa = base + (c % NS) * STG;
        uint32_t sbb = sa + AST;

        if (NS == 3) {   // 3-stage: prefetch before compute (stage (c-1)%3, readers done)
            if (c + 2 < NC) { load_chunk(c + 2); CP_COMMIT(); }
        }

        #pragma unroll
        for (int ks = 0; ks < 4; ks++) {
            uint32_t af[MI][4];
            #pragma unroll
            for (int mi = 0; mi < MI; mi++) {
                int row = a_row + mi * 16;
                int kc = ks * 2 + a_kc;
                LDSM4(af[mi], sa + row * 128 + ((kc ^ (row & 7)) * 16));
            }
            uint32_t bf[2][4];
            #pragma unroll
            for (int nj = 0; nj < 2; nj++) {
                int row = b_row + nj * 16;
                int kc = ks * 2 + b_kc;
                LDSM4(bf[nj], sbb + row * 128 + ((kc ^ (row & 7)) * 16));
            }
            #pragma unroll
            for (int mi = 0; mi < MI; mi++)
                #pragma unroll
                for (int ni = 0; ni < 4; ni++)
                    mma16816(acc[mi][ni], af[mi], bf[ni >> 1][(ni & 1) * 2],
                             bf[ni >> 1][(ni & 1) * 2 + 1]);
        }

        if (NS == 2) {   // 2-stage: next load overwrites the stage just read
            __syncthreads();
            if (c + 2 < NC) { load_chunk(c + 2); CP_COMMIT(); }
        }
    }

    int erow = bm * TM + wm * (TM / 2) + (lane >> 2);
    int ecol = bn * 128 + wn * 32 + (lane & 3) * 2;
    #pragma unroll
    for (int mi = 0; mi < MI; mi++) {
        #pragma unroll
        for (int ni = 0; ni < 4; ni++) {
            int r0 = erow + mi * 16, r1 = r0 + 8;
            int col = ecol + ni * 8;
            float b0 = 0.0f, b1 = 0.0f;
            if (a.bias) { b0 = a.bias[col]; b1 = a.bias[col + 1]; }
            float v0 = acc[mi][ni][0] + b0, v1 = acc[mi][ni][1] + b1;
            float v2 = acc[mi][ni][2] + b0, v3 = acc[mi][ni][3] + b1;
            if (a.addrow) {
                const float* t0 = a.addrow + (size_t)(r0 >> 2) * N + col;
                const float* t1 = a.addrow + (size_t)(r1 >> 2) * N + col;
                v0 += t0[0]; v1 += t0[1]; v2 += t1[0]; v3 += t1[1];
            }
            if (a.gelu) { v0 = gelu_tanh(v0); v1 = gelu_tanh(v1);
                          v2 = gelu_tanh(v2); v3 = gelu_tanh(v3); }
            if (a.outb) {
                *(__nv_bfloat162*)(a.outb + (size_t)r0 * N + col) = __floats2bfloat162_rn(v0, v1);
                *(__nv_bfloat162*)(a.outb + (size_t)r1 * N + col) = __floats2bfloat162_rn(v2, v3);
            } else {
                *(float2*)(a.outf + (size_t)r0 * N + col) = make_float2(v0, v1);
                *(float2*)(a.outf + (size_t)r1 * N + col) = make_float2(v2, v3);
            }
        }
    }
}

// ---------------- fused top-4 + emb gather/LN (block = 2 coarse rows) ----------------
__global__ void topk_emb_kernel(const float* __restrict__ coarse, int* __restrict__ idx,
                                const float* __restrict__ emb,
                                const float* __restrict__ g, const float* __restrict__ b,
                                __nv_bfloat16* __restrict__ e) {
    __shared__ int sidx[8];
    int t = threadIdx.x, warp = t >> 5, lane = t & 31;
    int b0 = blockIdx.x * 2;

    if (warp < 2) {
        int row = b0 + warp;
        const float* cr = coarse + (size_t)row * N_SZ;
        float4 a = ((const float4*)cr)[lane * 2];
        float4 bb = ((const float4*)cr)[lane * 2 + 1];
        float v[8] = {a.x, a.y, a.z, a.w, bb.x, bb.y, bb.z, bb.w};
        int base = lane * 8;
        #pragma unroll
        for (int k = 0; k < K_TOP; k++) {
            float bv = v[0]; int bi = 0;
            #pragma unroll
            for (int j = 1; j < 8; j++) if (v[j] > bv) { bv = v[j]; bi = j; }
            int bcol = base + bi;
            #pragma unroll
            for (int o = 16; o; o >>= 1) {
                float ov = __shfl_down_sync(0xffffffffu, bv, o);
                int   oc = __shfl_down_sync(0xffffffffu, bcol, o);
                if (ov > bv || (ov == bv && oc < bcol)) { bv = ov; bcol = oc; }
            }
            bcol = __shfl_sync(0xffffffffu, bcol, 0);
            if (lane == 0) { idx[row * K_TOP + k] = bcol; sidx[warp * K_TOP + k] = bcol; }
            if (bcol >= base && bcol < base + 8) v[bcol - base] = -INFINITY;
        }
    }
    __syncthreads();

    // 8 warps: (b,k) rows b0*4 .. b0*4+7
    int r = b0 * K_TOP + warp;
    int n = sidx[warp];
    const float4* er = (const float4*)(emb + (size_t)n * C_SZ);
    float4 v[4];
    float s = 0.0f, sq = 0.0f;
    #pragma unroll
    for (int j = 0; j < 4; j++) {
        v[j] = er[lane + 32 * j];
        s  += v[j].x + v[j].y + v[j].z + v[j].w;
        sq += v[j].x * v[j].x + v[j].y * v[j].y + v[j].z * v[j].z + v[j].w * v[j].w;
    }
    s = warp_sum(s); sq = warp_sum(sq);
    float mean = s * (1.0f / C_SZ);
    float var  = sq * (1.0f / C_SZ) - mean * mean;
    float rstd = rsqrtf(var + 1e-5f);
    __nv_bfloat16* eo = e + (size_t)r * C_SZ;
    #pragma unroll
    for (int j = 0; j < 4; j++) {
        float4 gg = ((const float4*)g)[lane + 32 * j];
        float4 bb = ((const float4*)b)[lane + 32 * j];
        float y0 = (v[j].x - mean) * rstd * gg.x + bb.x;
        float y1 = (v[j].y - mean) * rstd * gg.y + bb.y;
        float y2 = (v[j].z - mean) * rstd * gg.z + bb.z;
        float y3 = (v[j].w - mean) * rstd * gg.w + bb.w;
        __nv_bfloat162* wp = (__nv_bfloat162*)(eo + (lane + 32 * j) * 4);
        wp[0] = __floats2bfloat162_rn(y0, y1);
        wp[1] = __floats2bfloat162_rn(y2, y3);
    }
}

// ---------------- fused log-softmax + scatter of top-k cells into out ----------------
__global__ void scatter_vals(const float* __restrict__ fine, const float* __restrict__ coarse,
                             const int* __restrict__ idx, float* __restrict__ out) {
    int warp = threadIdx.x >> 5, lane = threadIdx.x & 31;
    int r = blockIdx.x * 8 + warp;
    int b = r >> 2;
    int n = idx[r];
    const float4* fr = (const float4*)(fine + (size_t)r * F_SZ);
    float4 a = fr[lane * 2], c = fr[lane * 2 + 1];
    float v[8] = {a.x, a.y, a.z, a.w, c.x, c.y, c.z, c.w};
    float m = v[0];
    #pragma unroll
    for (int j = 1; j < 8; j++) m = fmaxf(m, v[j]);
    m = warp_max(m);
    float s = 0.0f;
    #pragma unroll
    for (int j = 0; j < 8; j++) s += expf(v[j] - m);
    s = warp_sum(s);
    float add = coarse[(size_t)b * N_SZ + n] - m - logf(s);
    int ch0 = n >> 4, ch1 = n & 15;
    size_t obase = (size_t)b * 65537 + 1 + (size_t)ch0 * 4096 + ch1 * 16;
    #pragma unroll
    for (int q = 0; q < 8; q++) {
        int j = lane * 8 + q;
        out[obase + (size_t)(j >> 4) * 256 + (j & 15)] = v[q] + add;
    }
}

// ---------------- launch ----------------
extern "C" void kernel_launch(void* const* d_in, const int* in_sizes, int n_in,
                              void* d_out, int out_size) {
    const float* x     = (const float*)d_in[0];
    const float* in_g  = (const float*)d_in[1];
    const float* in_b  = (const float*)d_in[2];
    const float* nop_w = (const float*)d_in[3];
    const float* nop_b = (const float*)d_in[4];
    const float* c_w1  = (const float*)d_in[5];
    const float* c_b1  = (const float*)d_in[6];
    const float* c_w2  = (const float*)d_in[7];
    const float* c_b2  = (const float*)d_in[8];
    const float* c_w3  = (const float*)d_in[9];
    const float* c_b3  = (const float*)d_in[10];
    const float* emb   = (const float*)d_in[11];
    const float* emb_g = (const float*)d_in[12];
    const float* emb_b = (const float*)d_in[13];
    const float* f_w1  = (const float*)d_in[14];
    const float* f_b1  = (const float*)d_in[15];
    const float* f_w2  = (const float*)d_in[16];
    const float* f_b2  = (const float*)d_in[17];
    const float* f_w3  = (const float*)d_in[18];
    const float* f_b3  = (const float*)d_in[19];
    float* out = (float*)d_out;

    __nv_bfloat16 *xn, *h1, *h2, *e, *g1, *g2, *wbf;
    float *coarse, *fine, *t1;
    int *idx;
    cudaGetSymbolAddress((void**)&xn,     g_xn);
    cudaGetSymbolAddress((void**)&h1,     g_h1);
    cudaGetSymbolAddress((void**)&h2,     g_h2);
    cudaGetSymbolAddress((void**)&coarse, g_coarse);
    cudaGetSymbolAddress((void**)&idx,    g_topidx);
    cudaGetSymbolAddress((void**)&t1,     g_t1);
    cudaGetSymbolAddress((void**)&e,      g_e);
    cudaGetSymbolAddress((void**)&g1,     g_g1);
    cudaGetSymbolAddress((void**)&g2,     g_g2);
    cudaGetSymbolAddress((void**)&fine,   g_fine);
    cudaGetSymbolAddress((void**)&wbf,    g_wbf);

    const int SMEM32 = 2 * (32 * 128 + 16384) + 1024;   // 41984 (2-stage)
    const int SMEM64 = 3 * (64 * 128 + 16384) + 1024;   // 74752 (3-stage)
    cudaFuncSetAttribute((const void*)gemm_mma<32, 2>,
                         cudaFuncAttributeMaxDynamicSharedMemorySize, SMEM32);
    cudaFuncSetAttribute((const void*)gemm_mma<64, 3>,
                         cudaFuncAttributeMaxDynamicSharedMemorySize, SMEM64);

    // fused weight cvt + LN (+ no_op head): 1536 cvt tiles + 1024 LN blocks
    {
        CvtArgs ca;
        const float*   srcs[7] = {c_w1, c_w2, c_w3, f_w1, f_w1 + 512 * 512, f_w2, f_w3};
        __nv_bfloat16* dsts[7] = {wbf + W_CW1, wbf + W_CW2, wbf + W_CW3, wbf + W_FW1A,
                                  wbf + W_FW1B, wbf + W_FW2, wbf + W_FW3};
        int Ks[7] = {512, 512, 512, 512, 512, 512, 512};
        int Ns[7] = {512, 512, 256, 512, 512, 512, 256};
        int st = 0;
        for (int s = 0; s < 7; s++) {
            ca.W[s] = srcs[s]; ca.Wt[s] = dsts[s]; ca.K[s] = Ks[s]; ca.N[s] = Ns[s];
            ca.start[s] = st;
            st += (Ks[s] >> 5) * (Ns[s] >> 5);
        }
        prep_kernel<<<1536 + 1024, 256>>>(ca, x, in_g, in_b, nop_w, nop_b, xn, out);
    }

    GArgs Z = {};
    FillArgs FZ = {};
    // coarse GEMM1 + t1 pair (TM=32, 2-stage, 512 CTAs = 1 wave at 4/SM)
    {
        GArgs a0 = Z, a1 = Z;
        a0.A = xn; a0.Bw = wbf + W_CW1; a0.bias = c_b1; a0.outb = h1;
        a0.K = 512; a0.N = 512; a0.gridn = 4; a0.gelu = 1;
        a1.A = xn; a1.Bw = wbf + W_FW1A; a1.outf = t1;
        a1.K = 512; a1.N = 512; a1.gridn = 4; a1.gelu = 0;
        gemm_mma<32, 2><<<512, GT_THREADS, SMEM32>>>(a0, a1, 256, 512, FZ);
    }
    // coarse GEMM2
    {
        GArgs a = Z;
        a.A = h1; a.Bw = wbf + W_CW2; a.bias = c_b2; a.outb = h2;
        a.K = 512; a.N = 512; a.gridn = 4; a.gelu = 1;
        gemm_mma<32, 2><<<256, GT_THREADS, SMEM32>>>(a, a, 256, 256, FZ);
    }
    // coarse GEMM3 -> coarse (fp32)
    {
        GArgs a = Z;
        a.A = h2; a.Bw = wbf + W_CW3; a.bias = c_b3; a.outf = coarse;
        a.K = 512; a.N = 256; a.gridn = 2; a.gelu = 0;
        gemm_mma<32, 2><<<128, GT_THREADS, SMEM32>>>(a, a, 128, 128, FZ);
    }

    // fused top-4 + emb gather/LN
    topk_emb_kernel<<<B_SZ / 2, 256>>>(coarse, idx, emb, emb_g, emb_b, e);

    // fine GEMM1/GEMM2 (TM=64, 3-stage) with 148 background fill CTAs each (GEMM-majority mix)
    {
        GArgs a = Z;
        a.A = e; a.Bw = wbf + W_FW1B; a.bias = f_b1; a.addrow = t1; a.outb = g1;
        a.K = 512; a.N = 512; a.gridn = 4; a.gelu = 1;
        FillArgs fa = {coarse, out, 0, 148, 1600};
        gemm_mma<64, 3><<<148 + 512, GT_THREADS, SMEM64>>>(a, a, 512, 512, fa);
    }
    {
        GArgs a = Z;
        a.A = g1; a.Bw = wbf + W_FW2; a.bias = f_b2; a.outb = g2;
        a.K = 512; a.N = 512; a.gridn = 4; a.gelu = 1;
        FillArgs fa = {coarse, out, 1600, 148, 1600};
        gemm_mma<64, 3><<<148 + 512, GT_THREADS, SMEM64>>>(a, a, 512, 512, fa);
    }
    // fine GEMM3 + remaining 4992 fill tiles appended
    {
        GArgs a = Z;
        a.A = g2; a.Bw = wbf + W_FW3; a.bias = f_b3; a.outf = fine;
        a.K = 512; a.N = 256; a.gridn = 2; a.gelu = 0;
        FillArgs fa = {coarse, out, 3200, 0, 0};
        gemm_mma<64, 3><<<256 + 4992, GT_THREADS, SMEM64>>>(a, a, 256, 256, fa);
    }

    // scatter overwrites the top-k cells after all fill wrote them (same stream)
    scatter_vals<<<B_SZ * K_TOP / 8, 256>>>(fine, coarse, idx, out);
}